// round 11
// baseline (speedup 1.0000x reference)
#include <cuda_runtime.h>
#include <cstdint>
#include <cstddef>

// Problem constants
#define HID    512
#define NOBJC  151
#define NRELC  51
#define POOL   4096

// ---------------- k1 (edge_rep) constants ----------------
#define ASTR 36
#define BSTR 136
#define K1_SMEM ((2*128*ASTR + 2*32*BSTR) * 4)

// ---------------- k2 constants ----------------
// Block tile BM=128, BN=256, BK=16, 4 cp.async stages.
// 512 threads = 16 warps as 2x8 grid, warp tile 64x32 (acc[4][4][4] = 64 regs).
// V/W epilogue tiles are UNIONED with the stage buffers (time-disjoint) so the
// CTA fits in 110KB smem -> 2 CTAs/SM -> 8 warps/SMSP.
#define A2STR 20      // A stage tile [128 rows][16 k] padded to 20 words/row
#define B2STR 264     // B stage tile [16 k][256 n] padded to 264 words/row
#define VSTR  132
#define WSTR  72

#define ABUF (128*A2STR*4)   // 10240 B
#define BBUF (16*B2STR*4)    // 16896 B
#define OFFA 0
#define OFFB (4*ABUF)                    // 40960
// V/W union the same region as the A/B stages:
#define OFFV 0
#define OFFW (128*VSTR*4)                // 67584 (V+W = 104448 <= 108544 stage bytes)
#define OFFI (4*ABUF + 4*BBUF)           // 108544
#define K2S  (OFFI + 3*128*4)            // 110080

// Prepared (pre-rounded tf32) weight copies + materialized edge_rep
__device__ float g_edge_rep[(size_t)8192 * 1024];   // tf32-rounded
__device__ float g_wpc[(size_t)1024 * 4096];        // tf32-rounded W_post_cat
__device__ float g_wctx[(size_t)1024 * 256];        // tf32-rounded W_ctx, zero-padded

// ---------------------------------------------------------------------------
__device__ __forceinline__ unsigned f2tf(float f) {
    unsigned u;
    asm("cvt.rna.tf32.f32 %0, %1;" : "=r"(u) : "f"(f));
    return u;
}
__device__ __forceinline__ uint32_t s2u(const void* p) {
    uint32_t a;
    asm("{ .reg .u64 t; cvta.to.shared.u64 t, %1; cvt.u32.u64 %0, t; }" : "=r"(a) : "l"(p));
    return a;
}
__device__ __forceinline__ void cp16(uint32_t dst, const void* src) {
    asm volatile("cp.async.cg.shared.global [%0], [%1], 16;" :: "r"(dst), "l"(src));
}
__device__ __forceinline__ void cp_commit() {
    asm volatile("cp.async.commit_group;" ::: "memory");
}
__device__ __forceinline__ void cp_wait2() {
    asm volatile("cp.async.wait_group 2;" ::: "memory");
}
__device__ __forceinline__ void mma8(float (&d)[4], const unsigned (&a)[4], const unsigned (&b)[2]) {
    asm volatile(
        "mma.sync.aligned.m16n8k8.row.col.f32.tf32.tf32.f32 "
        "{%0,%1,%2,%3},{%4,%5,%6,%7},{%8,%9},{%0,%1,%2,%3};\n"
        : "+f"(d[0]), "+f"(d[1]), "+f"(d[2]), "+f"(d[3])
        : "r"(a[0]), "r"(a[1]), "r"(a[2]), "r"(a[3]), "r"(b[0]), "r"(b[1]));
}

// ===========================================================================
// Kernel 0: pre-round weights to tf32 bit patterns (so k2 can raw-copy them)
// ===========================================================================
__global__ void k0_prep(const float* __restrict__ Wpc, const float* __restrict__ Wctx) {
    int bid = blockIdx.x, tid = threadIdx.x;
    if (bid < 4096) {
        int idx = bid * 256 + tid;
        float4 v = __ldg((const float4*)Wpc + idx);
        float4 o;
        o.x = __uint_as_float(f2tf(v.x));
        o.y = __uint_as_float(f2tf(v.y));
        o.z = __uint_as_float(f2tf(v.z));
        o.w = __uint_as_float(f2tf(v.w));
        ((float4*)g_wpc)[idx] = o;
    } else {
        int idx = (bid - 4096) * 256 + tid;   // < 262144
        int k = idx >> 8, c = idx & 255;
        float v = (c < NRELC) ? __uint_as_float(f2tf(__ldg(Wctx + (size_t)k * NRELC + c))) : 0.f;
        g_wctx[idx] = v;
    }
}

// ===========================================================================
// Kernel 1: edge_rep = tf32round(edge_ctx @ W_post_emb + b)   (legacy tf32 mma)
// ===========================================================================
__device__ __forceinline__ void stA1(unsigned* __restrict__ Ab, const float4 (&ra)[4], int tid) {
#pragma unroll
    for (int i = 0; i < 4; i++) {
        int s = tid + i * 256, r = s >> 3, kq = s & 7;
        unsigned* p = Ab + r * ASTR + kq * 4;
        p[0] = f2tf(ra[i].x); p[1] = f2tf(ra[i].y); p[2] = f2tf(ra[i].z); p[3] = f2tf(ra[i].w);
    }
}
__device__ __forceinline__ void stB1(unsigned* __restrict__ Bb, const float4 (&rb)[4], int tid) {
#pragma unroll
    for (int i = 0; i < 4; i++) {
        int s = tid + i * 256, kk = s >> 5, cq = s & 31;
        unsigned* p = Bb + kk * BSTR + cq * 4;
        p[0] = f2tf(rb[i].x); p[1] = f2tf(rb[i].y); p[2] = f2tf(rb[i].z); p[3] = f2tf(rb[i].w);
    }
}
__device__ __forceinline__ void mma_tile1(float (&acc)[4][4][4], const unsigned* __restrict__ Ab,
                                          const unsigned* __restrict__ Bb, int wr, int wc, int lane) {
#pragma unroll
    for (int ks = 0; ks < 4; ks++) {
        unsigned af[4][4], bf[4][2];
#pragma unroll
        for (int tm = 0; tm < 4; tm++) {
            const unsigned* p = Ab + (wr * 64 + tm * 16 + (lane >> 2)) * ASTR + ks * 8 + (lane & 3);
            af[tm][0] = p[0]; af[tm][1] = p[8 * ASTR]; af[tm][2] = p[4]; af[tm][3] = p[8 * ASTR + 4];
        }
#pragma unroll
        for (int tn = 0; tn < 4; tn++) {
            const unsigned* p = Bb + (ks * 8 + (lane & 3)) * BSTR + wc * 32 + tn * 8 + (lane >> 2);
            bf[tn][0] = p[0]; bf[tn][1] = p[4 * BSTR];
        }
#pragma unroll
        for (int tm = 0; tm < 4; tm++)
#pragma unroll
            for (int tn = 0; tn < 4; tn++) mma8(acc[tm][tn], af[tm], bf[tn]);
    }
}

__global__ void __launch_bounds__(256, 1) k1_edge_rep(
    const float* __restrict__ A, const float* __restrict__ B, const float* __restrict__ bias) {
    extern __shared__ unsigned sm1[];
    unsigned* As = sm1;
    unsigned* Bs = sm1 + 2 * 128 * ASTR;
    const int tid = threadIdx.x, lane = tid & 31, wid = tid >> 5;
    const int wr = wid >> 2, wc = wid & 3;
    const int m0 = blockIdx.x * 128, n0 = blockIdx.y * 128;

    float acc[4][4][4];
#pragma unroll
    for (int a = 0; a < 4; a++)
#pragma unroll
        for (int b = 0; b < 4; b++)
#pragma unroll
            for (int c = 0; c < 4; c++) acc[a][b][c] = 0.f;

    float4 ra[4], rb[4];
#pragma unroll
    for (int i = 0; i < 4; i++) {
        int s = tid + i * 256;
        { int r = s >> 3, kq = s & 7;
          ra[i] = __ldg((const float4*)(A + (size_t)(m0 + r) * HID + kq * 4)); }
        { int kk = s >> 5, cq = s & 31;
          rb[i] = __ldg((const float4*)(B + (size_t)kk * 1024 + n0 + cq * 4)); }
    }
    stA1(As, ra, tid); stB1(Bs, rb, tid);
    __syncthreads();

    int buf = 0;
    for (int kt = 0; kt < 16; kt++) {
        if (kt < 15) {
            int k0 = (kt + 1) * 32;
#pragma unroll
            for (int i = 0; i < 4; i++) {
                int s = tid + i * 256;
                { int r = s >> 3, kq = s & 7;
                  ra[i] = __ldg((const float4*)(A + (size_t)(m0 + r) * HID + k0 + kq * 4)); }
                { int kk = s >> 5, cq = s & 31;
                  rb[i] = __ldg((const float4*)(B + (size_t)(k0 + kk) * 1024 + n0 + cq * 4)); }
            }
        }
        mma_tile1(acc, As + buf * 128 * ASTR, Bs + buf * 32 * BSTR, wr, wc, lane);
        if (kt < 15) { stA1(As + (buf ^ 1) * 128 * ASTR, ra, tid); stB1(Bs + (buf ^ 1) * 32 * BSTR, rb, tid); }
        __syncthreads();
        buf ^= 1;
    }

#pragma unroll
    for (int tm = 0; tm < 4; tm++) {
        int r = m0 + wr * 64 + tm * 16 + (lane >> 2);
#pragma unroll
        for (int tn = 0; tn < 4; tn++) {
            int c = n0 + wc * 32 + tn * 8 + 2 * (lane & 3);
            float2 bb = *(const float2*)(bias + c);
            float2 v0, v1;
            v0.x = __uint_as_float(f2tf(acc[tm][tn][0] + bb.x));
            v0.y = __uint_as_float(f2tf(acc[tm][tn][1] + bb.y));
            v1.x = __uint_as_float(f2tf(acc[tm][tn][2] + bb.x));
            v1.y = __uint_as_float(f2tf(acc[tm][tn][3] + bb.y));
            *(float2*)(g_edge_rep + (size_t)r * 1024 + c) = v0;
            *(float2*)(g_edge_rep + (size_t)(r + 8) * 1024 + c) = v1;
        }
    }
}

// ===========================================================================
// Kernel 2: fused gather -> (prod@Wpc+b)*U -> @Wrel (+prod@Wctx via virtual
// tile) -> +biases+freq. 512 threads, 2 CTAs/SM, V/W unioned with stages.
// ===========================================================================
__global__ void __launch_bounds__(512, 2) k2_main(
    const int* __restrict__ pair_idx, const int* __restrict__ obj_preds,
    const float* __restrict__ U,
    const float* __restrict__ bpc,
    const float* __restrict__ Wrel, const float* __restrict__ brel,
    const float* __restrict__ bctx,
    const float* __restrict__ freq, float* __restrict__ out) {
    extern __shared__ char smem[];
    const uint32_t sbu = s2u(smem);
    const float* er = g_edge_rep;

    const int tid = threadIdx.x, lane = tid & 31, wid = tid >> 5;
    const int wr = wid >> 3, wc = wid & 7;     // 2 x 8 warp grid
    const int m0 = blockIdx.x * 128;

    int* rows0 = (int*)(smem + OFFI);
    int* rows1 = rows0 + 128;
    int* pp    = rows1 + 128;

    if (tid < 128) {
        int i = m0 + tid;
        int p0 = pair_idx[2 * i], p1 = pair_idx[2 * i + 1];
        rows0[tid] = p0; rows1[tid] = p1;
        pp[tid] = obj_preds[p0] * NOBJC + obj_preds[p1];
    }
    __syncthreads();

    // Per-thread staging indices (constant across k-chunks)
    int raT[2], aoff, asubk;
    { int r = tid >> 2, kq = tid & 3;
      raT[0] = rows0[r]; raT[1] = rows1[r];
      aoff = (r * A2STR + kq * 4) * 4; asubk = kq * 4; }
    int boff[2], bk[2], bc[2];
#pragma unroll
    for (int i = 0; i < 2; i++) {
        int s = tid + i * 512;
        bk[i] = s >> 6; bc[i] = (s & 63) * 4;
        boff[i] = (bk[i] * B2STR + (s & 63) * 4) * 4;
    }

    // Persistent second-GEMM accumulator: 128x64, warp tile 64x8
    float acc2[4][4];
#pragma unroll
    for (int a = 0; a < 4; a++)
#pragma unroll
        for (int c = 0; c < 4; c++) acc2[a][c] = 0.f;

    for (int nt = 0; nt < 17; nt++) {
        const float* gB = (nt < 16) ? g_wpc : g_wctx;
        const size_t  gstride = (nt < 16) ? 4096 : 256;
        const int     nb = (nt < 16) ? nt * 256 : 0;

        float acc[4][4][4];
#pragma unroll
        for (int a = 0; a < 4; a++)
#pragma unroll
            for (int b = 0; b < 4; b++)
#pragma unroll
                for (int c = 0; c < 4; c++) acc[a][b][c] = 0.f;

        // ---- prologue: stages 0..2 ----
#pragma unroll
        for (int p = 0; p < 3; p++) {
            const int k0 = p * 16;
            uint32_t abase = sbu + OFFA + p * ABUF;
            uint32_t bbase = sbu + OFFB + p * BBUF;
            cp16(abase + aoff, er + (size_t)raT[0] * 1024 + k0 + asubk);
#pragma unroll
            for (int i = 0; i < 2; i++)
                cp16(bbase + boff[i], gB + (size_t)(k0 + bk[i]) * gstride + nb + bc[i]);
            cp_commit();
        }

        // ---- main loop: 64 k-chunks of 16 ----
        for (int kc = 0; kc < 64; kc++) {
            cp_wait2();
            __syncthreads();
            if (kc < 61) {
                const int kn = kc + 3, k0 = kn * 16;
                const int st = kn & 3;
                uint32_t abase = sbu + OFFA + st * ABUF;
                uint32_t bbase = sbu + OFFB + st * BBUF;
                cp16(abase + aoff, er + (size_t)raT[(k0 >= HID) ? 1 : 0] * 1024 + k0 + asubk);
#pragma unroll
                for (int i = 0; i < 2; i++)
                    cp16(bbase + boff[i], gB + (size_t)(k0 + bk[i]) * gstride + nb + bc[i]);
            }
            cp_commit();

            const unsigned* Ab = (const unsigned*)(smem + OFFA + (kc & 3) * ABUF);
            const unsigned* Bb = (const unsigned*)(smem + OFFB + (kc & 3) * BBUF);
#pragma unroll
            for (int ks = 0; ks < 2; ks++) {
                unsigned af[4][4], bf[4][2];
#pragma unroll
                for (int tm = 0; tm < 4; tm++) {
                    const unsigned* p = Ab + (wr * 64 + tm * 16 + (lane >> 2)) * A2STR + ks * 8 + (lane & 3);
                    af[tm][0] = p[0]; af[tm][1] = p[8 * A2STR];
                    af[tm][2] = p[4]; af[tm][3] = p[8 * A2STR + 4];
                }
#pragma unroll
                for (int tn = 0; tn < 4; tn++) {
                    const unsigned* p = Bb + (ks * 8 + (lane & 3)) * B2STR + wc * 32 + tn * 8 + (lane >> 2);
                    bf[tn][0] = p[0]; bf[tn][1] = p[4 * B2STR];
                }
#pragma unroll
                for (int tm = 0; tm < 4; tm++)
#pragma unroll
                    for (int tn = 0; tn < 4; tn++)
                        mma8(acc[tm][tn], af[tm], bf[tn]);
            }
        }
        __syncthreads();   // all stage buffers consumed; safe to reuse as V/W

        // ---- epilogue per 128-col half ----
        unsigned* Vs = (unsigned*)(smem + OFFV);
        unsigned* Ws = (unsigned*)(smem + OFFW);
        const int nhmax = (nt < 16) ? 2 : 1;
        for (int nh = 0; nh < nhmax; nh++) {
            // V store (owning warps: wc>>2 == nh), cols (wc&3)*32 + tn*8 + ...
            if ((wc >> 2) == nh) {
                const int clb = (wc & 3) * 32;
#pragma unroll
                for (int tm = 0; tm < 4; tm++) {
                    int rl = wr * 64 + tm * 16 + (lane >> 2);
                    if (nt < 16) {
                        const float* u0p = U + (size_t)(m0 + rl) * POOL + nt * 256 + nh * 128;
                        const float* u1p = u0p + 8 * POOL;
#pragma unroll
                        for (int tn = 0; tn < 4; tn++) {
                            int vcol = clb + tn * 8 + 2 * (lane & 3);
                            int nG = nt * 256 + nh * 128 + vcol;
                            float2 bb = *(const float2*)(bpc + nG);
                            float2 u0 = __ldg((const float2*)(u0p + vcol));
                            float2 u1 = __ldg((const float2*)(u1p + vcol));
                            Vs[rl * VSTR + vcol]           = f2tf((acc[tm][tn][0] + bb.x) * u0.x);
                            Vs[rl * VSTR + vcol + 1]       = f2tf((acc[tm][tn][1] + bb.y) * u0.y);
                            Vs[(rl + 8) * VSTR + vcol]     = f2tf((acc[tm][tn][2] + bb.x) * u1.x);
                            Vs[(rl + 8) * VSTR + vcol + 1] = f2tf((acc[tm][tn][3] + bb.y) * u1.y);
                        }
                    } else {
#pragma unroll
                        for (int tn = 0; tn < 4; tn++) {
                            int vcol = clb + tn * 8 + 2 * (lane & 3);
                            Vs[rl * VSTR + vcol]           = f2tf(acc[tm][tn][0]);
                            Vs[rl * VSTR + vcol + 1]       = f2tf(acc[tm][tn][1]);
                            Vs[(rl + 8) * VSTR + vcol]     = f2tf(acc[tm][tn][2]);
                            Vs[(rl + 8) * VSTR + vcol + 1] = f2tf(acc[tm][tn][3]);
                        }
                    }
                }
            }
            // Ws store (all 512 threads): [128 k][64 n]
            if (nt < 16) {
                const int n0h = nt * 256 + nh * 128;
#pragma unroll 4
                for (int i = 0; i < 16; i++) {
                    int s = tid + i * 512, k = s >> 6, c = s & 63;
                    float v = (c < NRELC) ? __ldg(Wrel + (size_t)(n0h + k) * NRELC + c) : 0.f;
                    Ws[k * WSTR + c] = f2tf(v);
                }
            } else {
#pragma unroll 4
                for (int i = 0; i < 16; i++) {
                    int s = tid + i * 512, k = s >> 6, c = s & 63;
                    Ws[k * WSTR + c] = (k == c && c < NRELC) ? 0x3F800000u : 0u;
                }
            }
            __syncthreads();

            // acc2 += V(128x128) @ Ws(128x64); warp tile 64x8
#pragma unroll
            for (int kk = 0; kk < 16; kk++) {
                unsigned af[4][4], bf[2];
#pragma unroll
                for (int tm = 0; tm < 4; tm++) {
                    const unsigned* p = Vs + (wr * 64 + tm * 16 + (lane >> 2)) * VSTR + kk * 8 + (lane & 3);
                    af[tm][0] = p[0]; af[tm][1] = p[8 * VSTR];
                    af[tm][2] = p[4]; af[tm][3] = p[8 * VSTR + 4];
                }
                {
                    const unsigned* p = Ws + (kk * 8 + (lane & 3)) * WSTR + wc * 8 + (lane >> 2);
                    bf[0] = p[0]; bf[1] = p[4 * WSTR];
                }
#pragma unroll
                for (int tm = 0; tm < 4; tm++)
                    mma8(acc2[tm], af[tm], bf);
            }
            __syncthreads();
        }
    }

    // ---- final epilogue: + b_rel + b_ctx + freq_table[pair_pred] ----
#pragma unroll
    for (int tm = 0; tm < 4; tm++) {
        int rl = wr * 64 + tm * 16 + (lane >> 2);
        int c = wc * 8 + 2 * (lane & 3);
#pragma unroll
        for (int q = 0; q < 4; q++) {
            int row = rl + ((q >= 2) ? 8 : 0);
            int col = c + (q & 1);
            if (col < NRELC) {
                float v = acc2[tm][q] + __ldg(brel + col) + __ldg(bctx + col)
                        + __ldg(freq + (size_t)pp[row] * NRELC + col);
                out[(size_t)(m0 + row) * NRELC + col] = v;
            }
        }
    }
}

// ===========================================================================
// Launch
// ===========================================================================
extern "C" void kernel_launch(void* const* d_in, const int* in_sizes, int n_in,
                              void* d_out, int out_size) {
    (void)in_sizes; (void)n_in; (void)out_size;
    const float* edge_ctx  = (const float*)d_in[0];
    const int*   obj_preds = (const int*)d_in[1];
    const int*   pair_idx  = (const int*)d_in[2];
    const float* U         = (const float*)d_in[3];
    const float* Wpe       = (const float*)d_in[4];
    const float* bpe       = (const float*)d_in[5];
    const float* Wpc       = (const float*)d_in[6];
    const float* bpc       = (const float*)d_in[7];
    const float* Wrel      = (const float*)d_in[8];
    const float* brel      = (const float*)d_in[9];
    const float* Wctx      = (const float*)d_in[10];
    const float* bctx      = (const float*)d_in[11];
    const float* freq      = (const float*)d_in[12];
    float* out = (float*)d_out;

    cudaFuncSetAttribute(k1_edge_rep, cudaFuncAttributeMaxDynamicSharedMemorySize, K1_SMEM);
    cudaFuncSetAttribute(k2_main,     cudaFuncAttributeMaxDynamicSharedMemorySize, K2S);

    k0_prep<<<4096 + 1024, 256>>>(Wpc, Wctx);
    k1_edge_rep<<<dim3(64, 8), 256, K1_SMEM>>>(edge_ctx, Wpe, bpe);
    k2_main<<<512, 512, K2S>>>(pair_idx, obj_preds, U, bpc,
                               Wrel, brel, bctx, freq, out);
}

// round 13
// speedup vs baseline: 5.2016x; 5.2016x over previous
#include <cuda_runtime.h>
#include <cstdint>
#include <cstddef>

// Problem constants
#define HID    512
#define NOBJC  151
#define NRELC  51
#define POOL   4096

// ---------------- k1 (edge_rep) constants ----------------
#define ASTR 36
#define BSTR 136
#define K1_SMEM ((2*128*ASTR + 2*32*BSTR) * 4)

// ---------------- k2 constants ----------------
// Block tile BM=128, BN=256, BK=16, 4 cp.async stages.
// 512 threads = 16 warps as 2x8 grid, warp tile 64x32 (acc[4][4][4] = 64 regs).
// 1 CTA/SM (regs ~128/thread), 4 warps per SMSP for latency hiding.
// V/W epilogue tiles are UNIONED with the stage buffers (time-disjoint).
#define A2STR 20      // A stage tile [128 rows][16 k] padded to 20 words/row
#define B2STR 264     // B stage tile [16 k][256 n] padded to 264 words/row
#define VSTR  132
#define WSTR  72

#define ABUF (128*A2STR*4)   // 10240 B
#define BBUF (16*B2STR*4)    // 16896 B
#define OFFA 0
#define OFFB (4*ABUF)                    // 40960
// V/W union the same region as the A/B stages:
#define OFFV 0
#define OFFW (128*VSTR*4)                // 67584 (V+W = 104448 <= 108544 stage bytes)
#define OFFI (4*ABUF + 4*BBUF)           // 108544
#define K2S  (OFFI + 3*128*4)            // 110080

// Prepared (pre-rounded tf32) weight copies + materialized edge_rep
__device__ float g_edge_rep[(size_t)8192 * 1024];   // tf32-rounded
__device__ float g_wpc[(size_t)1024 * 4096];        // tf32-rounded W_post_cat
__device__ float g_wctx[(size_t)1024 * 256];        // tf32-rounded W_ctx, zero-padded

// ---------------------------------------------------------------------------
__device__ __forceinline__ unsigned f2tf(float f) {
    unsigned u;
    asm("cvt.rna.tf32.f32 %0, %1;" : "=r"(u) : "f"(f));
    return u;
}
__device__ __forceinline__ uint32_t s2u(const void* p) {
    uint32_t a;
    asm("{ .reg .u64 t; cvta.to.shared.u64 t, %1; cvt.u32.u64 %0, t; }" : "=r"(a) : "l"(p));
    return a;
}
__device__ __forceinline__ void cp16(uint32_t dst, const void* src) {
    asm volatile("cp.async.cg.shared.global [%0], [%1], 16;" :: "r"(dst), "l"(src));
}
__device__ __forceinline__ void cp_commit() {
    asm volatile("cp.async.commit_group;" ::: "memory");
}
__device__ __forceinline__ void cp_wait2() {
    asm volatile("cp.async.wait_group 2;" ::: "memory");
}
__device__ __forceinline__ void mma8(float (&d)[4], const unsigned (&a)[4], const unsigned (&b)[2]) {
    asm volatile(
        "mma.sync.aligned.m16n8k8.row.col.f32.tf32.tf32.f32 "
        "{%0,%1,%2,%3},{%4,%5,%6,%7},{%8,%9},{%0,%1,%2,%3};\n"
        : "+f"(d[0]), "+f"(d[1]), "+f"(d[2]), "+f"(d[3])
        : "r"(a[0]), "r"(a[1]), "r"(a[2]), "r"(a[3]), "r"(b[0]), "r"(b[1]));
}

// ===========================================================================
// Kernel 0: pre-round weights to tf32 bit patterns (so k2 can raw-copy them)
// ===========================================================================
__global__ void k0_prep(const float* __restrict__ Wpc, const float* __restrict__ Wctx) {
    int bid = blockIdx.x, tid = threadIdx.x;
    if (bid < 4096) {
        int idx = bid * 256 + tid;
        float4 v = __ldg((const float4*)Wpc + idx);
        float4 o;
        o.x = __uint_as_float(f2tf(v.x));
        o.y = __uint_as_float(f2tf(v.y));
        o.z = __uint_as_float(f2tf(v.z));
        o.w = __uint_as_float(f2tf(v.w));
        ((float4*)g_wpc)[idx] = o;
    } else {
        int idx = (bid - 4096) * 256 + tid;   // < 262144
        int k = idx >> 8, c = idx & 255;
        float v = (c < NRELC) ? __uint_as_float(f2tf(__ldg(Wctx + (size_t)k * NRELC + c))) : 0.f;
        g_wctx[idx] = v;
    }
}

// ===========================================================================
// Kernel 1: edge_rep = tf32round(edge_ctx @ W_post_emb + b)   (legacy tf32 mma)
// ===========================================================================
__device__ __forceinline__ void stA1(unsigned* __restrict__ Ab, const float4 (&ra)[4], int tid) {
#pragma unroll
    for (int i = 0; i < 4; i++) {
        int s = tid + i * 256, r = s >> 3, kq = s & 7;
        unsigned* p = Ab + r * ASTR + kq * 4;
        p[0] = f2tf(ra[i].x); p[1] = f2tf(ra[i].y); p[2] = f2tf(ra[i].z); p[3] = f2tf(ra[i].w);
    }
}
__device__ __forceinline__ void stB1(unsigned* __restrict__ Bb, const float4 (&rb)[4], int tid) {
#pragma unroll
    for (int i = 0; i < 4; i++) {
        int s = tid + i * 256, kk = s >> 5, cq = s & 31;
        unsigned* p = Bb + kk * BSTR + cq * 4;
        p[0] = f2tf(rb[i].x); p[1] = f2tf(rb[i].y); p[2] = f2tf(rb[i].z); p[3] = f2tf(rb[i].w);
    }
}
__device__ __forceinline__ void mma_tile1(float (&acc)[4][4][4], const unsigned* __restrict__ Ab,
                                          const unsigned* __restrict__ Bb, int wr, int wc, int lane) {
#pragma unroll
    for (int ks = 0; ks < 4; ks++) {
        unsigned af[4][4], bf[4][2];
#pragma unroll
        for (int tm = 0; tm < 4; tm++) {
            const unsigned* p = Ab + (wr * 64 + tm * 16 + (lane >> 2)) * ASTR + ks * 8 + (lane & 3);
            af[tm][0] = p[0]; af[tm][1] = p[8 * ASTR]; af[tm][2] = p[4]; af[tm][3] = p[8 * ASTR + 4];
        }
#pragma unroll
        for (int tn = 0; tn < 4; tn++) {
            const unsigned* p = Bb + (ks * 8 + (lane & 3)) * BSTR + wc * 32 + tn * 8 + (lane >> 2);
            bf[tn][0] = p[0]; bf[tn][1] = p[4 * BSTR];
        }
#pragma unroll
        for (int tm = 0; tm < 4; tm++)
#pragma unroll
            for (int tn = 0; tn < 4; tn++) mma8(acc[tm][tn], af[tm], bf[tn]);
    }
}

__global__ void __launch_bounds__(256, 1) k1_edge_rep(
    const float* __restrict__ A, const float* __restrict__ B, const float* __restrict__ bias) {
    extern __shared__ unsigned sm1[];
    unsigned* As = sm1;
    unsigned* Bs = sm1 + 2 * 128 * ASTR;
    const int tid = threadIdx.x, lane = tid & 31, wid = tid >> 5;
    const int wr = wid >> 2, wc = wid & 3;
    const int m0 = blockIdx.x * 128, n0 = blockIdx.y * 128;

    float acc[4][4][4];
#pragma unroll
    for (int a = 0; a < 4; a++)
#pragma unroll
        for (int b = 0; b < 4; b++)
#pragma unroll
            for (int c = 0; c < 4; c++) acc[a][b][c] = 0.f;

    float4 ra[4], rb[4];
#pragma unroll
    for (int i = 0; i < 4; i++) {
        int s = tid + i * 256;
        { int r = s >> 3, kq = s & 7;
          ra[i] = __ldg((const float4*)(A + (size_t)(m0 + r) * HID + kq * 4)); }
        { int kk = s >> 5, cq = s & 31;
          rb[i] = __ldg((const float4*)(B + (size_t)kk * 1024 + n0 + cq * 4)); }
    }
    stA1(As, ra, tid); stB1(Bs, rb, tid);
    __syncthreads();

    int buf = 0;
    for (int kt = 0; kt < 16; kt++) {
        if (kt < 15) {
            int k0 = (kt + 1) * 32;
#pragma unroll
            for (int i = 0; i < 4; i++) {
                int s = tid + i * 256;
                { int r = s >> 3, kq = s & 7;
                  ra[i] = __ldg((const float4*)(A + (size_t)(m0 + r) * HID + k0 + kq * 4)); }
                { int kk = s >> 5, cq = s & 31;
                  rb[i] = __ldg((const float4*)(B + (size_t)(k0 + kk) * 1024 + n0 + cq * 4)); }
            }
        }
        mma_tile1(acc, As + buf * 128 * ASTR, Bs + buf * 32 * BSTR, wr, wc, lane);
        if (kt < 15) { stA1(As + (buf ^ 1) * 128 * ASTR, ra, tid); stB1(Bs + (buf ^ 1) * 32 * BSTR, rb, tid); }
        __syncthreads();
        buf ^= 1;
    }

#pragma unroll
    for (int tm = 0; tm < 4; tm++) {
        int r = m0 + wr * 64 + tm * 16 + (lane >> 2);
#pragma unroll
        for (int tn = 0; tn < 4; tn++) {
            int c = n0 + wc * 32 + tn * 8 + 2 * (lane & 3);
            float2 bb = *(const float2*)(bias + c);
            float2 v0, v1;
            v0.x = __uint_as_float(f2tf(acc[tm][tn][0] + bb.x));
            v0.y = __uint_as_float(f2tf(acc[tm][tn][1] + bb.y));
            v1.x = __uint_as_float(f2tf(acc[tm][tn][2] + bb.x));
            v1.y = __uint_as_float(f2tf(acc[tm][tn][3] + bb.y));
            *(float2*)(g_edge_rep + (size_t)r * 1024 + c) = v0;
            *(float2*)(g_edge_rep + (size_t)(r + 8) * 1024 + c) = v1;
        }
    }
}

// ===========================================================================
// Kernel 2: fused gather -> (prod@Wpc+b)*U -> @Wrel (+prod@Wctx via virtual
// tile) -> +biases+freq. 512 threads, 1 CTA/SM (128-reg budget, no hot spills),
// 4 warps/SMSP, V/W unioned with stages.
// ===========================================================================
__global__ void __launch_bounds__(512) k2_main(
    const int* __restrict__ pair_idx, const int* __restrict__ obj_preds,
    const float* __restrict__ U,
    const float* __restrict__ bpc,
    const float* __restrict__ Wrel, const float* __restrict__ brel,
    const float* __restrict__ bctx,
    const float* __restrict__ freq, float* __restrict__ out) {
    extern __shared__ char smem[];
    const uint32_t sbu = s2u(smem);
    const float* er = g_edge_rep;

    const int tid = threadIdx.x, lane = tid & 31, wid = tid >> 5;
    const int wr = wid >> 3, wc = wid & 7;     // 2 x 8 warp grid
    const int m0 = blockIdx.x * 128;

    int* rows0 = (int*)(smem + OFFI);
    int* rows1 = rows0 + 128;
    int* pp    = rows1 + 128;

    if (tid < 128) {
        int i = m0 + tid;
        int p0 = pair_idx[2 * i], p1 = pair_idx[2 * i + 1];
        rows0[tid] = p0; rows1[tid] = p1;
        pp[tid] = obj_preds[p0] * NOBJC + obj_preds[p1];
    }
    __syncthreads();

    // Per-thread staging indices (constant across k-chunks)
    int raT[2], aoff, asubk;
    { int r = tid >> 2, kq = tid & 3;
      raT[0] = rows0[r]; raT[1] = rows1[r];
      aoff = (r * A2STR + kq * 4) * 4; asubk = kq * 4; }
    int boff[2], bk[2], bc[2];
#pragma unroll
    for (int i = 0; i < 2; i++) {
        int s = tid + i * 512;
        bk[i] = s >> 6; bc[i] = (s & 63) * 4;
        boff[i] = (bk[i] * B2STR + (s & 63) * 4) * 4;
    }

    // Persistent second-GEMM accumulator: 128x64, warp tile 64x8
    float acc2[4][4];
#pragma unroll
    for (int a = 0; a < 4; a++)
#pragma unroll
        for (int c = 0; c < 4; c++) acc2[a][c] = 0.f;

    for (int nt = 0; nt < 17; nt++) {
        const float* gB = (nt < 16) ? g_wpc : g_wctx;
        const size_t  gstride = (nt < 16) ? 4096 : 256;
        const int     nb = (nt < 16) ? nt * 256 : 0;

        float acc[4][4][4];
#pragma unroll
        for (int a = 0; a < 4; a++)
#pragma unroll
            for (int b = 0; b < 4; b++)
#pragma unroll
                for (int c = 0; c < 4; c++) acc[a][b][c] = 0.f;

        // ---- prologue: stages 0..2 ----
#pragma unroll
        for (int p = 0; p < 3; p++) {
            const int k0 = p * 16;
            uint32_t abase = sbu + OFFA + p * ABUF;
            uint32_t bbase = sbu + OFFB + p * BBUF;
            cp16(abase + aoff, er + (size_t)raT[0] * 1024 + k0 + asubk);
#pragma unroll
            for (int i = 0; i < 2; i++)
                cp16(bbase + boff[i], gB + (size_t)(k0 + bk[i]) * gstride + nb + bc[i]);
            cp_commit();
        }

        // ---- main loop: 64 k-chunks of 16 ----
        for (int kc = 0; kc < 64; kc++) {
            cp_wait2();
            __syncthreads();
            if (kc < 61) {
                const int kn = kc + 3, k0 = kn * 16;
                const int st = kn & 3;
                uint32_t abase = sbu + OFFA + st * ABUF;
                uint32_t bbase = sbu + OFFB + st * BBUF;
                cp16(abase + aoff, er + (size_t)raT[(k0 >= HID) ? 1 : 0] * 1024 + k0 + asubk);
#pragma unroll
                for (int i = 0; i < 2; i++)
                    cp16(bbase + boff[i], gB + (size_t)(k0 + bk[i]) * gstride + nb + bc[i]);
            }
            cp_commit();

            const unsigned* Ab = (const unsigned*)(smem + OFFA + (kc & 3) * ABUF);
            const unsigned* Bb = (const unsigned*)(smem + OFFB + (kc & 3) * BBUF);
#pragma unroll
            for (int ks = 0; ks < 2; ks++) {
                unsigned af[4][4], bf[4][2];
#pragma unroll
                for (int tm = 0; tm < 4; tm++) {
                    const unsigned* p = Ab + (wr * 64 + tm * 16 + (lane >> 2)) * A2STR + ks * 8 + (lane & 3);
                    af[tm][0] = p[0]; af[tm][1] = p[8 * A2STR];
                    af[tm][2] = p[4]; af[tm][3] = p[8 * A2STR + 4];
                }
#pragma unroll
                for (int tn = 0; tn < 4; tn++) {
                    const unsigned* p = Bb + (ks * 8 + (lane & 3)) * B2STR + wc * 32 + tn * 8 + (lane >> 2);
                    bf[tn][0] = p[0]; bf[tn][1] = p[4 * B2STR];
                }
#pragma unroll
                for (int tm = 0; tm < 4; tm++)
#pragma unroll
                    for (int tn = 0; tn < 4; tn++)
                        mma8(acc[tm][tn], af[tm], bf[tn]);
            }
        }
        __syncthreads();   // all stage buffers consumed; safe to reuse as V/W

        // ---- epilogue per 128-col half ----
        unsigned* Vs = (unsigned*)(smem + OFFV);
        unsigned* Ws = (unsigned*)(smem + OFFW);
        const int nhmax = (nt < 16) ? 2 : 1;
        for (int nh = 0; nh < nhmax; nh++) {
            // V store (owning warps: wc>>2 == nh), cols (wc&3)*32 + tn*8 + ...
            if ((wc >> 2) == nh) {
                const int clb = (wc & 3) * 32;
#pragma unroll
                for (int tm = 0; tm < 4; tm++) {
                    int rl = wr * 64 + tm * 16 + (lane >> 2);
                    if (nt < 16) {
                        const float* u0p = U + (size_t)(m0 + rl) * POOL + nt * 256 + nh * 128;
                        const float* u1p = u0p + 8 * POOL;
#pragma unroll
                        for (int tn = 0; tn < 4; tn++) {
                            int vcol = clb + tn * 8 + 2 * (lane & 3);
                            int nG = nt * 256 + nh * 128 + vcol;
                            float2 bb = *(const float2*)(bpc + nG);
                            float2 u0 = __ldg((const float2*)(u0p + vcol));
                            float2 u1 = __ldg((const float2*)(u1p + vcol));
                            Vs[rl * VSTR + vcol]           = f2tf((acc[tm][tn][0] + bb.x) * u0.x);
                            Vs[rl * VSTR + vcol + 1]       = f2tf((acc[tm][tn][1] + bb.y) * u0.y);
                            Vs[(rl + 8) * VSTR + vcol]     = f2tf((acc[tm][tn][2] + bb.x) * u1.x);
                            Vs[(rl + 8) * VSTR + vcol + 1] = f2tf((acc[tm][tn][3] + bb.y) * u1.y);
                        }
                    } else {
#pragma unroll
                        for (int tn = 0; tn < 4; tn++) {
                            int vcol = clb + tn * 8 + 2 * (lane & 3);
                            Vs[rl * VSTR + vcol]           = f2tf(acc[tm][tn][0]);
                            Vs[rl * VSTR + vcol + 1]       = f2tf(acc[tm][tn][1]);
                            Vs[(rl + 8) * VSTR + vcol]     = f2tf(acc[tm][tn][2]);
                            Vs[(rl + 8) * VSTR + vcol + 1] = f2tf(acc[tm][tn][3]);
                        }
                    }
                }
            }
            // Ws store (all 512 threads): [128 k][64 n]
            if (nt < 16) {
                const int n0h = nt * 256 + nh * 128;
#pragma unroll 4
                for (int i = 0; i < 16; i++) {
                    int s = tid + i * 512, k = s >> 6, c = s & 63;
                    float v = (c < NRELC) ? __ldg(Wrel + (size_t)(n0h + k) * NRELC + c) : 0.f;
                    Ws[k * WSTR + c] = f2tf(v);
                }
            } else {
#pragma unroll 4
                for (int i = 0; i < 16; i++) {
                    int s = tid + i * 512, k = s >> 6, c = s & 63;
                    Ws[k * WSTR + c] = (k == c && c < NRELC) ? 0x3F800000u : 0u;
                }
            }
            __syncthreads();

            // acc2 += V(128x128) @ Ws(128x64); warp tile 64x8
#pragma unroll
            for (int kk = 0; kk < 16; kk++) {
                unsigned af[4][4], bf[2];
#pragma unroll
                for (int tm = 0; tm < 4; tm++) {
                    const unsigned* p = Vs + (wr * 64 + tm * 16 + (lane >> 2)) * VSTR + kk * 8 + (lane & 3);
                    af[tm][0] = p[0]; af[tm][1] = p[8 * VSTR];
                    af[tm][2] = p[4]; af[tm][3] = p[8 * VSTR + 4];
                }
                {
                    const unsigned* p = Ws + (kk * 8 + (lane & 3)) * WSTR + wc * 8 + (lane >> 2);
                    bf[0] = p[0]; bf[1] = p[4 * WSTR];
                }
#pragma unroll
                for (int tm = 0; tm < 4; tm++)
                    mma8(acc2[tm], af[tm], bf);
            }
            __syncthreads();
        }
    }

    // ---- final epilogue: + b_rel + b_ctx + freq_table[pair_pred] ----
#pragma unroll
    for (int tm = 0; tm < 4; tm++) {
        int rl = wr * 64 + tm * 16 + (lane >> 2);
        int c = wc * 8 + 2 * (lane & 3);
#pragma unroll
        for (int q = 0; q < 4; q++) {
            int row = rl + ((q >= 2) ? 8 : 0);
            int col = c + (q & 1);
            if (col < NRELC) {
                float v = acc2[tm][q] + __ldg(brel + col) + __ldg(bctx + col)
                        + __ldg(freq + (size_t)pp[row] * NRELC + col);
                out[(size_t)(m0 + row) * NRELC + col] = v;
            }
        }
    }
}

// ===========================================================================
// Launch
// ===========================================================================
extern "C" void kernel_launch(void* const* d_in, const int* in_sizes, int n_in,
                              void* d_out, int out_size) {
    (void)in_sizes; (void)n_in; (void)out_size;
    const float* edge_ctx  = (const float*)d_in[0];
    const int*   obj_preds = (const int*)d_in[1];
    const int*   pair_idx  = (const int*)d_in[2];
    const float* U         = (const float*)d_in[3];
    const float* Wpe       = (const float*)d_in[4];
    const float* bpe       = (const float*)d_in[5];
    const float* Wpc       = (const float*)d_in[6];
    const float* bpc       = (const float*)d_in[7];
    const float* Wrel      = (const float*)d_in[8];
    const float* brel      = (const float*)d_in[9];
    const float* Wctx      = (const float*)d_in[10];
    const float* bctx      = (const float*)d_in[11];
    const float* freq      = (const float*)d_in[12];
    float* out = (float*)d_out;

    cudaFuncSetAttribute(k1_edge_rep, cudaFuncAttributeMaxDynamicSharedMemorySize, K1_SMEM);
    cudaFuncSetAttribute(k2_main,     cudaFuncAttributeMaxDynamicSharedMemorySize, K2S);

    k0_prep<<<4096 + 1024, 256>>>(Wpc, Wctx);
    k1_edge_rep<<<dim3(64, 8), 256, K1_SMEM>>>(edge_ctx, Wpe, bpe);
    k2_main<<<512, 512, K2S>>>(pair_idx, obj_preds, U, bpc,
                               Wrel, brel, bctx, freq, out);
}

// round 14
// speedup vs baseline: 7.7899x; 1.4976x over previous
#include <cuda_runtime.h>
#include <cstdint>
#include <cstddef>

// Problem constants
#define HID    512
#define NOBJC  151
#define NRELC  51
#define POOL   4096
#define NREL   65536

// ---------------- k1 (edge_rep) constants ----------------
#define ASTR 36
#define BSTR 136
#define K1_SMEM ((2*128*ASTR + 2*32*BSTR) * 4)

// ---------------- k2 constants ----------------
// BM=128, BN=128, BK=32, 3-stage cp.async, 256 threads (8 warps, 2x4),
// warp tile 64x32. 2 CTAs/SM (smem 108.5KB, regs capped 128).
// Grid 2048 = 512 m-tiles x 4 n-splits; partials combined via atomicAdd.
#define ABUF (128*ASTR*4)          // 18432 B per stage
#define BBUF (32*BSTR*4)           // 17408 B per stage
#define STG  (ABUF + BBUF)         // 35840
#define VSTR 132
#define WSTR 72
// V/W union the stage region (time-disjoint):
#define OFFV 0
#define OFFW (128*VSTR*4)          // 67584 ; V+W = 104448 <= 3*STG = 107520
#define OFFI (3*STG)               // 107520
#define K2S  (OFFI + 2*128*4)      // 108544

// Prepared (pre-rounded tf32) buffers
__device__ float g_edge_rep[(size_t)8192 * 1024];   // tf32-rounded
__device__ float g_wpc[(size_t)1024 * 4096];        // tf32-rounded W_post_cat
__device__ float g_wctx[(size_t)1024 * 256];        // tf32-rounded W_ctx, zero-padded

// ---------------------------------------------------------------------------
__device__ __forceinline__ unsigned f2tf(float f) {
    unsigned u;
    asm("cvt.rna.tf32.f32 %0, %1;" : "=r"(u) : "f"(f));
    return u;
}
__device__ __forceinline__ uint32_t s2u(const void* p) {
    uint32_t a;
    asm("{ .reg .u64 t; cvta.to.shared.u64 t, %1; cvt.u32.u64 %0, t; }" : "=r"(a) : "l"(p));
    return a;
}
__device__ __forceinline__ void cp16(uint32_t dst, const void* src) {
    asm volatile("cp.async.cg.shared.global [%0], [%1], 16;" :: "r"(dst), "l"(src));
}
__device__ __forceinline__ void cp_commit() {
    asm volatile("cp.async.commit_group;" ::: "memory");
}
__device__ __forceinline__ void cp_wait1() {
    asm volatile("cp.async.wait_group 1;" ::: "memory");
}
__device__ __forceinline__ void mma8(float (&d)[4], const unsigned (&a)[4], const unsigned (&b)[2]) {
    asm volatile(
        "mma.sync.aligned.m16n8k8.row.col.f32.tf32.tf32.f32 "
        "{%0,%1,%2,%3},{%4,%5,%6,%7},{%8,%9},{%0,%1,%2,%3};\n"
        : "+f"(d[0]), "+f"(d[1]), "+f"(d[2]), "+f"(d[3])
        : "r"(a[0]), "r"(a[1]), "r"(a[2]), "r"(a[3]), "r"(b[0]), "r"(b[1]));
}

// ===========================================================================
// Kernel 0: pre-round weights to tf32 bit patterns
// ===========================================================================
__global__ void k0_prep(const float* __restrict__ Wpc, const float* __restrict__ Wctx) {
    int bid = blockIdx.x, tid = threadIdx.x;
    if (bid < 4096) {
        int idx = bid * 256 + tid;
        float4 v = __ldg((const float4*)Wpc + idx);
        float4 o;
        o.x = __uint_as_float(f2tf(v.x));
        o.y = __uint_as_float(f2tf(v.y));
        o.z = __uint_as_float(f2tf(v.z));
        o.w = __uint_as_float(f2tf(v.w));
        ((float4*)g_wpc)[idx] = o;
    } else {
        int idx = (bid - 4096) * 256 + tid;   // < 262144
        int k = idx >> 8, c = idx & 255;
        float v = (c < NRELC) ? __uint_as_float(f2tf(__ldg(Wctx + (size_t)k * NRELC + c))) : 0.f;
        g_wctx[idx] = v;
    }
}

// ===========================================================================
// Kernel init: out = b_rel + b_ctx + freq_table[pair_pred]
// ===========================================================================
__global__ void k_init(const int* __restrict__ pair_idx, const int* __restrict__ obj_preds,
                       const float* __restrict__ brel, const float* __restrict__ bctx,
                       const float* __restrict__ freq, float* __restrict__ out) {
    int idx = blockIdx.x * 256 + threadIdx.x;
    if (idx >= NREL * NRELC) return;
    int i = idx / NRELC;
    int c = idx - i * NRELC;
    int pp = __ldg(obj_preds + __ldg(pair_idx + 2 * i)) * NOBJC
           + __ldg(obj_preds + __ldg(pair_idx + 2 * i + 1));
    out[idx] = __ldg(brel + c) + __ldg(bctx + c) + __ldg(freq + (size_t)pp * NRELC + c);
}

// ===========================================================================
// Kernel 1: edge_rep = tf32round(edge_ctx @ W_post_emb + b)  (legacy tf32 mma)
// ===========================================================================
__device__ __forceinline__ void stA1(unsigned* __restrict__ Ab, const float4 (&ra)[4], int tid) {
#pragma unroll
    for (int i = 0; i < 4; i++) {
        int s = tid + i * 256, r = s >> 3, kq = s & 7;
        unsigned* p = Ab + r * ASTR + kq * 4;
        p[0] = f2tf(ra[i].x); p[1] = f2tf(ra[i].y); p[2] = f2tf(ra[i].z); p[3] = f2tf(ra[i].w);
    }
}
__device__ __forceinline__ void stB1(unsigned* __restrict__ Bb, const float4 (&rb)[4], int tid) {
#pragma unroll
    for (int i = 0; i < 4; i++) {
        int s = tid + i * 256, kk = s >> 5, cq = s & 31;
        unsigned* p = Bb + kk * BSTR + cq * 4;
        p[0] = f2tf(rb[i].x); p[1] = f2tf(rb[i].y); p[2] = f2tf(rb[i].z); p[3] = f2tf(rb[i].w);
    }
}
__device__ __forceinline__ void mma_tile(float (&acc)[4][4][4], const unsigned* __restrict__ Ab,
                                         const unsigned* __restrict__ Bb, int wr, int wc, int lane) {
#pragma unroll
    for (int ks = 0; ks < 4; ks++) {
        unsigned af[4][4], bf[4][2];
#pragma unroll
        for (int tm = 0; tm < 4; tm++) {
            const unsigned* p = Ab + (wr * 64 + tm * 16 + (lane >> 2)) * ASTR + ks * 8 + (lane & 3);
            af[tm][0] = p[0]; af[tm][1] = p[8 * ASTR]; af[tm][2] = p[4]; af[tm][3] = p[8 * ASTR + 4];
        }
#pragma unroll
        for (int tn = 0; tn < 4; tn++) {
            const unsigned* p = Bb + (ks * 8 + (lane & 3)) * BSTR + wc * 32 + tn * 8 + (lane >> 2);
            bf[tn][0] = p[0]; bf[tn][1] = p[4 * BSTR];
        }
#pragma unroll
        for (int tm = 0; tm < 4; tm++)
#pragma unroll
            for (int tn = 0; tn < 4; tn++) mma8(acc[tm][tn], af[tm], bf[tn]);
    }
}

__global__ void __launch_bounds__(256, 1) k1_edge_rep(
    const float* __restrict__ A, const float* __restrict__ B, const float* __restrict__ bias) {
    extern __shared__ unsigned sm1[];
    unsigned* As = sm1;
    unsigned* Bs = sm1 + 2 * 128 * ASTR;
    const int tid = threadIdx.x, lane = tid & 31, wid = tid >> 5;
    const int wr = wid >> 2, wc = wid & 3;
    const int m0 = blockIdx.x * 128, n0 = blockIdx.y * 128;

    float acc[4][4][4];
#pragma unroll
    for (int a = 0; a < 4; a++)
#pragma unroll
        for (int b = 0; b < 4; b++)
#pragma unroll
            for (int c = 0; c < 4; c++) acc[a][b][c] = 0.f;

    float4 ra[4], rb[4];
#pragma unroll
    for (int i = 0; i < 4; i++) {
        int s = tid + i * 256;
        { int r = s >> 3, kq = s & 7;
          ra[i] = __ldg((const float4*)(A + (size_t)(m0 + r) * HID + kq * 4)); }
        { int kk = s >> 5, cq = s & 31;
          rb[i] = __ldg((const float4*)(B + (size_t)kk * 1024 + n0 + cq * 4)); }
    }
    stA1(As, ra, tid); stB1(Bs, rb, tid);
    __syncthreads();

    int buf = 0;
    for (int kt = 0; kt < 16; kt++) {
        if (kt < 15) {
            int k0 = (kt + 1) * 32;
#pragma unroll
            for (int i = 0; i < 4; i++) {
                int s = tid + i * 256;
                { int r = s >> 3, kq = s & 7;
                  ra[i] = __ldg((const float4*)(A + (size_t)(m0 + r) * HID + k0 + kq * 4)); }
                { int kk = s >> 5, cq = s & 31;
                  rb[i] = __ldg((const float4*)(B + (size_t)(k0 + kk) * 1024 + n0 + cq * 4)); }
            }
        }
        mma_tile(acc, As + buf * 128 * ASTR, Bs + buf * 32 * BSTR, wr, wc, lane);
        if (kt < 15) { stA1(As + (buf ^ 1) * 128 * ASTR, ra, tid); stB1(Bs + (buf ^ 1) * 32 * BSTR, rb, tid); }
        __syncthreads();
        buf ^= 1;
    }

#pragma unroll
    for (int tm = 0; tm < 4; tm++) {
        int r = m0 + wr * 64 + tm * 16 + (lane >> 2);
#pragma unroll
        for (int tn = 0; tn < 4; tn++) {
            int c = n0 + wc * 32 + tn * 8 + 2 * (lane & 3);
            float2 bb = *(const float2*)(bias + c);
            float2 v0, v1;
            v0.x = __uint_as_float(f2tf(acc[tm][tn][0] + bb.x));
            v0.y = __uint_as_float(f2tf(acc[tm][tn][1] + bb.y));
            v1.x = __uint_as_float(f2tf(acc[tm][tn][2] + bb.x));
            v1.y = __uint_as_float(f2tf(acc[tm][tn][3] + bb.y));
            *(float2*)(g_edge_rep + (size_t)r * 1024 + c) = v0;
            *(float2*)(g_edge_rep + (size_t)(r + 8) * 1024 + c) = v1;
        }
    }
}

// ===========================================================================
// Kernel 2: per CTA = (m-tile, n-split of 4). 8 or 9 n-tiles of 128 cols.
// Main GEMM (BK=32, 3-stage cp.async) -> V=(G+b)*U -> acc2 += V@Wrel-chunk
// (virtual W_ctx tile via identity on split 3). atomicAdd partials into out.
// ===========================================================================
__global__ void __launch_bounds__(256, 2) k2_main(
    const int* __restrict__ pair_idx,
    const float* __restrict__ U,
    const float* __restrict__ bpc,
    const float* __restrict__ Wrel,
    float* __restrict__ out) {
    extern __shared__ char smem[];
    const uint32_t sbu = s2u(smem);
    const float* er = g_edge_rep;

    const int tid = threadIdx.x, lane = tid & 31, wid = tid >> 5;
    const int wr = wid >> 2, wc = wid & 3;       // 2 x 4 warp grid
    const int m0 = (blockIdx.x >> 2) * 128;
    const int ns = blockIdx.x & 3;
    const int ntiles = (ns == 3) ? 9 : 8;        // split 3 also owns the virtual tile

    int* rows0 = (int*)(smem + OFFI);
    int* rows1 = rows0 + 128;

    if (tid < 128) {
        int i = m0 + tid;
        rows0[tid] = pair_idx[2 * i];
        rows1[tid] = pair_idx[2 * i + 1];
    }
    __syncthreads();

    // Per-thread staging constants
    int raT[2][4], aoff[4], akq[4];
#pragma unroll
    for (int i = 0; i < 4; i++) {
        int s = tid + i * 256, r = s >> 3, kq = s & 7;
        raT[0][i] = rows0[r]; raT[1][i] = rows1[r];
        aoff[i] = (r * ASTR + kq * 4) * 4;
        akq[i] = kq * 4;
    }
    int boff[4], bkk[4], bco[4];
#pragma unroll
    for (int i = 0; i < 4; i++) {
        int s = tid + i * 256;
        bkk[i] = s >> 5;
        bco[i] = (s & 31) * 4;
        boff[i] = (bkk[i] * BSTR + bco[i]) * 4;
    }

    // Persistent partial accumulator: 128x64, warp tile 64x16
    // (dead through the main k-loop -> compiler spills it cold under the reg cap)
    float acc2[4][2][4];
#pragma unroll
    for (int a = 0; a < 4; a++)
#pragma unroll
        for (int b = 0; b < 2; b++)
#pragma unroll
            for (int c = 0; c < 4; c++) acc2[a][b][c] = 0.f;

    for (int jt = 0; jt < ntiles; jt++) {
        const int nt = (jt < 8) ? (ns * 8 + jt) : 32;   // global n-tile id
        const bool real = (nt < 32);
        const float* gB = real ? g_wpc : g_wctx;
        const size_t gstride = real ? 4096 : 256;
        const int nb = real ? nt * 128 : 0;

        float acc[4][4][4];
#pragma unroll
        for (int a = 0; a < 4; a++)
#pragma unroll
            for (int b = 0; b < 4; b++)
#pragma unroll
                for (int c = 0; c < 4; c++) acc[a][b][c] = 0.f;

        // ---- prologue: stages 0,1 (k0 = 0, 32; both < HID) ----
#pragma unroll
        for (int p = 0; p < 2; p++) {
            const int k0 = p * 32;
            uint32_t ab = sbu + p * STG;
            uint32_t bb = sbu + p * STG + ABUF;
#pragma unroll
            for (int i = 0; i < 4; i++)
                cp16(ab + aoff[i], er + (size_t)raT[0][i] * 1024 + k0 + akq[i]);
#pragma unroll
            for (int i = 0; i < 4; i++)
                cp16(bb + boff[i], gB + (size_t)(k0 + bkk[i]) * gstride + nb + bco[i]);
            cp_commit();
        }

        // ---- main loop: 32 chunks of BK=32 ----
        for (int kc = 0; kc < 32; kc++) {
            cp_wait1();
            __syncthreads();
            if (kc < 30) {
                const int k0 = (kc + 2) * 32;
                const int st = (kc + 2) % 3;
                const int h = (k0 >= HID) ? 1 : 0;
                uint32_t ab = sbu + st * STG;
                uint32_t bb = sbu + st * STG + ABUF;
#pragma unroll
                for (int i = 0; i < 4; i++)
                    cp16(ab + aoff[i], er + (size_t)raT[h][i] * 1024 + k0 + akq[i]);
#pragma unroll
                for (int i = 0; i < 4; i++)
                    cp16(bb + boff[i], gB + (size_t)(k0 + bkk[i]) * gstride + nb + bco[i]);
            }
            cp_commit();

            const int st = kc % 3;
            mma_tile(acc, (const unsigned*)(smem + st * STG),
                          (const unsigned*)(smem + st * STG + ABUF), wr, wc, lane);
        }
        __syncthreads();   // stages consumed; region reused as V/W

        // ---- epilogue: V = (G + bpc) * U  (or V = G for virtual tile) ----
        unsigned* Vs = (unsigned*)(smem + OFFV);
        unsigned* Ws = (unsigned*)(smem + OFFW);
        const int n0 = nt * 128;   // global col base for real tiles
#pragma unroll
        for (int tm = 0; tm < 4; tm++) {
            int rl = wr * 64 + tm * 16 + (lane >> 2);
            if (real) {
                const float* u0p = U + (size_t)(m0 + rl) * POOL + n0;
                const float* u1p = u0p + 8 * POOL;
#pragma unroll
                for (int tn = 0; tn < 4; tn++) {
                    int vcol = wc * 32 + tn * 8 + 2 * (lane & 3);
                    float2 bb = *(const float2*)(bpc + n0 + vcol);
                    float2 u0 = __ldg((const float2*)(u0p + vcol));
                    float2 u1 = __ldg((const float2*)(u1p + vcol));
                    Vs[rl * VSTR + vcol]           = f2tf((acc[tm][tn][0] + bb.x) * u0.x);
                    Vs[rl * VSTR + vcol + 1]       = f2tf((acc[tm][tn][1] + bb.y) * u0.y);
                    Vs[(rl + 8) * VSTR + vcol]     = f2tf((acc[tm][tn][2] + bb.x) * u1.x);
                    Vs[(rl + 8) * VSTR + vcol + 1] = f2tf((acc[tm][tn][3] + bb.y) * u1.y);
                }
            } else {
#pragma unroll
                for (int tn = 0; tn < 4; tn++) {
                    int vcol = wc * 32 + tn * 8 + 2 * (lane & 3);
                    Vs[rl * VSTR + vcol]           = f2tf(acc[tm][tn][0]);
                    Vs[rl * VSTR + vcol + 1]       = f2tf(acc[tm][tn][1]);
                    Vs[(rl + 8) * VSTR + vcol]     = f2tf(acc[tm][tn][2]);
                    Vs[(rl + 8) * VSTR + vcol + 1] = f2tf(acc[tm][tn][3]);
                }
            }
        }
        // Ws: [128 k][64 n] = Wrel chunk (or identity for the virtual tile)
        if (real) {
#pragma unroll 4
            for (int i = 0; i < 32; i++) {
                int s = tid + i * 256, k = s >> 6, c = s & 63;
                float v = (c < NRELC) ? __ldg(Wrel + (size_t)(n0 + k) * NRELC + c) : 0.f;
                Ws[k * WSTR + c] = f2tf(v);
            }
        } else {
#pragma unroll 4
            for (int i = 0; i < 32; i++) {
                int s = tid + i * 256, k = s >> 6, c = s & 63;
                Ws[k * WSTR + c] = (k == c && c < NRELC) ? 0x3F800000u : 0u;
            }
        }
        __syncthreads();

        // ---- acc2 += V(128x128) @ Ws(128x64) ----
#pragma unroll
        for (int kk = 0; kk < 16; kk++) {
            unsigned af[4][4], bf[2][2];
#pragma unroll
            for (int tm = 0; tm < 4; tm++) {
                const unsigned* p = Vs + (wr * 64 + tm * 16 + (lane >> 2)) * VSTR + kk * 8 + (lane & 3);
                af[tm][0] = p[0]; af[tm][1] = p[8 * VSTR];
                af[tm][2] = p[4]; af[tm][3] = p[8 * VSTR + 4];
            }
#pragma unroll
            for (int tn = 0; tn < 2; tn++) {
                const unsigned* p = Ws + (kk * 8 + (lane & 3)) * WSTR + wc * 16 + tn * 8 + (lane >> 2);
                bf[tn][0] = p[0]; bf[tn][1] = p[4 * WSTR];
            }
#pragma unroll
            for (int tm = 0; tm < 4; tm++)
#pragma unroll
                for (int tn = 0; tn < 2; tn++)
                    mma8(acc2[tm][tn], af[tm], bf[tn]);
        }
        __syncthreads();
    }

    // ---- combine partials: atomicAdd into pre-initialized out ----
#pragma unroll
    for (int tm = 0; tm < 4; tm++) {
        int rl = wr * 64 + tm * 16 + (lane >> 2);
#pragma unroll
        for (int tn = 0; tn < 2; tn++) {
            int c = wc * 16 + tn * 8 + 2 * (lane & 3);
#pragma unroll
            for (int q = 0; q < 4; q++) {
                int row = rl + ((q >= 2) ? 8 : 0);
                int col = c + (q & 1);
                if (col < NRELC)
                    atomicAdd(out + (size_t)(m0 + row) * NRELC + col, acc2[tm][tn][q]);
            }
        }
    }
}

// ===========================================================================
// Launch
// ===========================================================================
extern "C" void kernel_launch(void* const* d_in, const int* in_sizes, int n_in,
                              void* d_out, int out_size) {
    (void)in_sizes; (void)n_in; (void)out_size;
    const float* edge_ctx  = (const float*)d_in[0];
    const int*   obj_preds = (const int*)d_in[1];
    const int*   pair_idx  = (const int*)d_in[2];
    const float* U         = (const float*)d_in[3];
    const float* Wpe       = (const float*)d_in[4];
    const float* bpe       = (const float*)d_in[5];
    const float* Wpc       = (const float*)d_in[6];
    const float* bpc       = (const float*)d_in[7];
    const float* Wrel      = (const float*)d_in[8];
    const float* brel      = (const float*)d_in[9];
    const float* Wctx      = (const float*)d_in[10];
    const float* bctx      = (const float*)d_in[11];
    const float* freq      = (const float*)d_in[12];
    float* out = (float*)d_out;

    cudaFuncSetAttribute(k1_edge_rep, cudaFuncAttributeMaxDynamicSharedMemorySize, K1_SMEM);
    cudaFuncSetAttribute(k2_main,     cudaFuncAttributeMaxDynamicSharedMemorySize, K2S);

    k0_prep<<<4096 + 1024, 256>>>(Wpc, Wctx);
    k_init<<<(NREL * NRELC + 255) / 256, 256>>>(pair_idx, obj_preds, brel, bctx, freq, out);
    k1_edge_rep<<<dim3(64, 8), 256, K1_SMEM>>>(edge_ctx, Wpe, bpe);
    k2_main<<<2048, 256, K2S>>>(pair_idx, U, bpc, Wrel, out);
}